// round 4
// baseline (speedup 1.0000x reference)
#include <cuda_runtime.h>
#include <cstdint>
#include <math.h>

// ---------------------------------------------------------------------------
// Problem constants
//   output  [64,1000] f32, target [64] int, feats_a [3,64,65536] f32,
//   feats_b [4,64,32768] f32;   out = [loss(1), output(64000)] f32
// ---------------------------------------------------------------------------
#define NROW 64
#define NCLS 1000
#define FA 3
#define DA 65536
#define FB 4
#define DB 32768
#define BLKS_PER_A 29          // 3*29 = 87 blocks for group a
#define BLKS_PER_B 15          // 4*15 = 60 blocks for group b
#define GRID1 (FA * BLKS_PER_A + FB * BLKS_PER_B)   // 147 (one wave on 148 SMs)
#define TILES_A (DA / 64)      // 1024
#define TILES_B (DB / 64)      // 512

// Scratch (no allocations allowed -> __device__ globals)
__device__ float  g_part[GRID1][4096];   // per-block partial Gram matrices
__device__ double g_Kd[7][4096];         // final Gram matrices (diag zeroed), f64
__device__ double g_ce_row[NROW];        // per-row CE contributions

// ---------------------------------------------------------------------------
// Phase 1: partial Gram K = X X^T over a D-range, fp32 register tiles.
// 256 threads = 16x16 grid, each thread owns a 4x4 tile of the 64x64 output.
// Smem tile: 64 rows x 64 cols as float4 with XOR swizzle (a-frags broadcast,
// b-frags conflict-light). Register double-buffer for the global loads.
// ---------------------------------------------------------------------------
__global__ __launch_bounds__(256, 1) void gram_partial(
    const float* __restrict__ A, const float* __restrict__ B) {
    int b = blockIdx.x;
    const float* X;
    long long D;
    int t0, t1;
    if (b < FA * BLKS_PER_A) {
        int f = b / BLKS_PER_A, lb = b % BLKS_PER_A;
        X = A + (long long)f * NROW * DA;
        D = DA;
        t0 = lb * TILES_A / BLKS_PER_A;
        t1 = (lb + 1) * TILES_A / BLKS_PER_A;
    } else {
        int bb = b - FA * BLKS_PER_A;
        int f = bb / BLKS_PER_B, lb = bb % BLKS_PER_B;
        X = B + (long long)f * NROW * DB;
        D = DB;
        t0 = lb * TILES_B / BLKS_PER_B;
        t1 = (lb + 1) * TILES_B / BLKS_PER_B;
    }

    __shared__ float4 Xs[64][16];   // 16 KB

    int tid = threadIdx.x;
    int tx = tid & 15, ty = tid >> 4;

    float acc[4][4];
#pragma unroll
    for (int i = 0; i < 4; i++)
#pragma unroll
        for (int j = 0; j < 4; j++) acc[i][j] = 0.f;

    // prefetch first tile into registers
    float4 pf[4];
#pragma unroll
    for (int i = 0; i < 4; i++) {
        int idx = tid + i * 256;
        int row = idx >> 4, c4 = idx & 15;
        pf[i] = *(const float4*)(X + (long long)row * D + (long long)t0 * 64 + 4 * c4);
    }

    for (int tt = t0; tt < t1; tt++) {
        __syncthreads();
#pragma unroll
        for (int i = 0; i < 4; i++) {
            int idx = tid + i * 256;
            int row = idx >> 4, c4 = idx & 15;
            Xs[row][c4 ^ ((row >> 2) & 7)] = pf[i];
        }
        __syncthreads();
        if (tt + 1 < t1) {
#pragma unroll
            for (int i = 0; i < 4; i++) {
                int idx = tid + i * 256;
                int row = idx >> 4, c4 = idx & 15;
                pf[i] = *(const float4*)(X + (long long)row * D +
                                         (long long)(tt + 1) * 64 + 4 * c4);
            }
        }
#pragma unroll 4
        for (int k4 = 0; k4 < 16; k4++) {
            float4 af[4], bf[4];
#pragma unroll
            for (int i = 0; i < 4; i++) af[i] = Xs[4 * ty + i][k4 ^ (ty & 7)];
#pragma unroll
            for (int i = 0; i < 4; i++) bf[i] = Xs[4 * tx + i][k4 ^ (tx & 7)];
#pragma unroll
            for (int i = 0; i < 4; i++)
#pragma unroll
                for (int j = 0; j < 4; j++) {
                    acc[i][j] += af[i].x * bf[j].x;
                    acc[i][j] += af[i].y * bf[j].y;
                    acc[i][j] += af[i].z * bf[j].z;
                    acc[i][j] += af[i].w * bf[j].w;
                }
        }
    }

    float* P = g_part[b];
#pragma unroll
    for (int i = 0; i < 4; i++)
#pragma unroll
        for (int j = 0; j < 4; j++)
            P[(4 * ty + i) * 64 + 4 * tx + j] = acc[i][j];
}

// ---------------------------------------------------------------------------
// Phase 2: reduce partials -> K (double), zero the diagonal.
// ---------------------------------------------------------------------------
__global__ void gram_reduce() {
    int gid = blockIdx.x * 256 + threadIdx.x;
    int f = gid >> 12;
    int e = gid & 4095;
    int n = e >> 6, m = e & 63;
    double sum = 0.0;
    if (n != m) {
        int b0, nb;
        if (f < FA) { b0 = f * BLKS_PER_A; nb = BLKS_PER_A; }
        else        { b0 = FA * BLKS_PER_A + (f - FA) * BLKS_PER_B; nb = BLKS_PER_B; }
        for (int bb = 0; bb < nb; bb++) sum += (double)g_part[b0 + bb][e];
    }
    g_Kd[f][e] = sum;
}

// ---------------------------------------------------------------------------
// CE: one block per row. Target dtype detected on-device without any read
// past the minimal (int32) footprint: if the buffer is int64 (values<1000),
// every odd 32-bit word of the first 256 bytes is zero.
// ---------------------------------------------------------------------------
__global__ void ce_kernel(const float* __restrict__ logits,
                          const void* __restrict__ tgt_raw) {
    int row = blockIdx.x;
    const float* x = logits + row * NCLS;
    __shared__ float  redf[256];
    __shared__ double redd[256];
    int tid = threadIdx.x;

    float m = -1e30f;
    for (int c = tid; c < NCLS; c += 256) m = fmaxf(m, x[c]);
    redf[tid] = m;
    __syncthreads();
    for (int s = 128; s > 0; s >>= 1) {
        if (tid < s) redf[tid] = fmaxf(redf[tid], redf[tid + s]);
        __syncthreads();
    }
    float M = redf[0];
    __syncthreads();

    double se = 0.0;
    for (int c = tid; c < NCLS; c += 256) se += exp((double)(x[c] - M));
    redd[tid] = se;
    __syncthreads();
    for (int s = 128; s > 0; s >>= 1) {
        if (tid < s) redd[tid] += redd[tid + s];
        __syncthreads();
    }
    if (tid == 0) {
        // dtype sniff within the always-safe first 64 int32 words
        const int* ti = (const int*)tgt_raw;
        bool odd_zero = true;
        for (int k = 1; k < 64; k += 2) odd_zero &= (ti[k] == 0);
        long long t;
        if (odd_zero) t = ((const long long*)tgt_raw)[row];  // int64 layout
        else          t = (long long)ti[row];                // int32 layout
        if (t < 0 || t >= NCLS) t = 0;   // never fault; error shows as rel_err
        g_ce_row[row] = -((double)x[t] - (double)M - log(redd[0]));
    }
}

// ---------------------------------------------------------------------------
// Finalize: rowsums, total sums, tr(Ki Kj), unbiased HSIC, CKA, loss.
// ---------------------------------------------------------------------------
__device__ __forceinline__ double block_reduce(double v, double* red) {
    int tid = threadIdx.x;
    red[tid] = v;
    __syncthreads();
    for (int s = 128; s > 0; s >>= 1) {
        if (tid < s) red[tid] += red[tid + s];
        __syncthreads();
    }
    double r = red[0];
    __syncthreads();
    return r;
}

__global__ void finalize(float* __restrict__ out) {
    __shared__ double red[256];
    __shared__ double r_sh[7 * 64];
    __shared__ double s_sh[7];
    __shared__ double trkl_sh[25];
    int tid = threadIdx.x;

    for (int idx = tid; idx < 7 * 64; idx += 256) {
        int f = idx / 64, n = idx % 64;
        double rs = 0.0;
        for (int m = 0; m < 64; m++) rs += g_Kd[f][n * 64 + m];
        r_sh[idx] = rs;
    }
    __syncthreads();
    if (tid < 7) {
        double a = 0.0;
        for (int n = 0; n < 64; n++) a += r_sh[tid * 64 + n];
        s_sh[tid] = a;
    }
    __syncthreads();
    for (int p = 0; p < 25; p++) {
        int fi, fj;
        if (p < 9) { fi = p / 3; fj = p % 3; }
        else       { int q = p - 9; fi = 3 + q / 4; fj = 3 + q % 4; }
        double part = 0.0;
        for (int e = tid; e < 4096; e += 256) part += g_Kd[fi][e] * g_Kd[fj][e];
        double tot = block_reduce(part, red);
        if (tid == 0) trkl_sh[p] = tot;
        __syncthreads();
    }

    if (tid == 0) {
        const double c1 = 63.0 * 62.0;   // (N-1)(N-2)
        const double c2 = 62.0;          // (N-2)
        const double c3 = 64.0 * 61.0;   // N(N-3)
        double cka = 0.0;
        for (int g = 0; g < 2; g++) {
            int F = g ? 4 : 3;
            int base = g ? 3 : 0;
            int pbase = g ? 9 : 0;
            double hs[4][4], dd[4];
            for (int i = 0; i < F; i++)
                for (int j = 0; j < F; j++) {
                    double trkl = trkl_sh[pbase + i * F + j];
                    double rr = 0.0;
                    for (int n = 0; n < 64; n++)
                        rr += r_sh[(base + i) * 64 + n] * r_sh[(base + j) * 64 + n];
                    hs[i][j] = (trkl + s_sh[base + i] * s_sh[base + j] / c1 -
                                2.0 * rr / c2) / c3;
                }
            for (int i = 0; i < F; i++) dd[i] = sqrt(hs[i][i]);
            for (int i = 0; i < F; i++)
                for (int j = 0; j < F; j++)
                    cka += hs[i][j] / (dd[i] * dd[j]);
        }
        double ce = 0.0;
        for (int n = 0; n < NROW; n++) ce += g_ce_row[n];
        ce /= (double)NROW;
        out[0] = (float)(ce + 0.1 * cka);
    }
}

// ---------------------------------------------------------------------------
extern "C" void kernel_launch(void* const* d_in, const int* in_sizes, int n_in,
                              void* d_out, int out_size) {
    // Identify inputs by element count -- robust to metadata ordering.
    const float* logits = nullptr;
    const void*  tgt    = nullptr;
    const float* fa     = nullptr;
    const float* fb     = nullptr;
    for (int i = 0; i < n_in; i++) {
        int s = in_sizes[i];
        if (s == NROW * NCLS)           logits = (const float*)d_in[i];
        else if (s == NROW)             tgt    = d_in[i];
        else if (s == FA * NROW * DA)   fa     = (const float*)d_in[i];
        else if (s == FB * NROW * DB)   fb     = (const float*)d_in[i];
    }
    float* out = (float*)d_out;

    ce_kernel<<<NROW, 256>>>(logits, tgt);
    gram_partial<<<GRID1, 256>>>(fa, fb);
    gram_reduce<<<112, 256>>>();
    finalize<<<1, 256>>>(out);
    // passthrough of `output` (second tuple element)
    cudaMemcpyAsync(out + 1, logits, NROW * NCLS * sizeof(float),
                    cudaMemcpyDeviceToDevice, 0);
}

// round 5
// speedup vs baseline: 1.3667x; 1.3667x over previous
#include <cuda_runtime.h>
#include <cstdint>
#include <math.h>

// ---------------------------------------------------------------------------
// Problem constants
//   output  [64,1000] f32, target [64] int, feats_a [3,64,65536] f32,
//   feats_b [4,64,32768] f32;   out = [loss(1), output(64000)] f32
// ---------------------------------------------------------------------------
#define NROW 64
#define NCLS 1000
#define FA 3
#define DA 65536
#define FB 4
#define DB 32768
#define BLKS_PER_A 29          // 3*29 = 87 blocks for group a
#define BLKS_PER_B 15          // 4*15 = 60 blocks for group b
#define GRID1 (FA * BLKS_PER_A + FB * BLKS_PER_B)   // 147 (one wave on 148 SMs)
#define TILES_A (DA / 64)      // 1024
#define TILES_B (DB / 64)      // 512

// Scratch (no allocations allowed -> __device__ globals)
__device__ float  g_part[GRID1][4096];   // per-block partial Gram matrices
__device__ double g_Kd[7][4096];         // final Gram matrices (diag zeroed), f64
__device__ double g_ce_row[NROW];        // per-row CE contributions
__device__ double g_trkl[25];            // tr(Ki Kj) per in-group pair
__device__ double g_rsum[7][64];         // row sums of each K

// ---------------------------------------------------------------------------
// Phase 1: partial Gram K = X X^T over a D-range, fp32 register tiles.
// 256 threads = 16x16 grid, each thread owns a 4x4 tile of the 64x64 output.
// ---------------------------------------------------------------------------
__global__ __launch_bounds__(256, 1) void gram_partial(
    const float* __restrict__ A, const float* __restrict__ B) {
    int b = blockIdx.x;
    const float* X;
    long long D;
    int t0, t1;
    if (b < FA * BLKS_PER_A) {
        int f = b / BLKS_PER_A, lb = b % BLKS_PER_A;
        X = A + (long long)f * NROW * DA;
        D = DA;
        t0 = lb * TILES_A / BLKS_PER_A;
        t1 = (lb + 1) * TILES_A / BLKS_PER_A;
    } else {
        int bb = b - FA * BLKS_PER_A;
        int f = bb / BLKS_PER_B, lb = bb % BLKS_PER_B;
        X = B + (long long)f * NROW * DB;
        D = DB;
        t0 = lb * TILES_B / BLKS_PER_B;
        t1 = (lb + 1) * TILES_B / BLKS_PER_B;
    }

    __shared__ float4 Xs[64][16];   // 16 KB

    int tid = threadIdx.x;
    int tx = tid & 15, ty = tid >> 4;

    float acc[4][4];
#pragma unroll
    for (int i = 0; i < 4; i++)
#pragma unroll
        for (int j = 0; j < 4; j++) acc[i][j] = 0.f;

    // prefetch first tile into registers
    float4 pf[4];
#pragma unroll
    for (int i = 0; i < 4; i++) {
        int idx = tid + i * 256;
        int row = idx >> 4, c4 = idx & 15;
        pf[i] = *(const float4*)(X + (long long)row * D + (long long)t0 * 64 + 4 * c4);
    }

    for (int tt = t0; tt < t1; tt++) {
        __syncthreads();
#pragma unroll
        for (int i = 0; i < 4; i++) {
            int idx = tid + i * 256;
            int row = idx >> 4, c4 = idx & 15;
            Xs[row][c4 ^ ((row >> 2) & 7)] = pf[i];
        }
        __syncthreads();
        if (tt + 1 < t1) {
#pragma unroll
            for (int i = 0; i < 4; i++) {
                int idx = tid + i * 256;
                int row = idx >> 4, c4 = idx & 15;
                pf[i] = *(const float4*)(X + (long long)row * D +
                                         (long long)(tt + 1) * 64 + 4 * c4);
            }
        }
#pragma unroll 4
        for (int k4 = 0; k4 < 16; k4++) {
            float4 af[4], bf[4];
#pragma unroll
            for (int i = 0; i < 4; i++) af[i] = Xs[4 * ty + i][k4 ^ (ty & 7)];
#pragma unroll
            for (int i = 0; i < 4; i++) bf[i] = Xs[4 * tx + i][k4 ^ (tx & 7)];
#pragma unroll
            for (int i = 0; i < 4; i++)
#pragma unroll
                for (int j = 0; j < 4; j++) {
                    acc[i][j] += af[i].x * bf[j].x;
                    acc[i][j] += af[i].y * bf[j].y;
                    acc[i][j] += af[i].z * bf[j].z;
                    acc[i][j] += af[i].w * bf[j].w;
                }
        }
    }

    float* P = g_part[b];
#pragma unroll
    for (int i = 0; i < 4; i++)
#pragma unroll
        for (int j = 0; j < 4; j++)
            P[(4 * ty + i) * 64 + 4 * tx + j] = acc[i][j];
}

// ---------------------------------------------------------------------------
// Phase 2: reduce partials -> K (double), zero the diagonal.
// ---------------------------------------------------------------------------
__global__ void gram_reduce() {
    int gid = blockIdx.x * 256 + threadIdx.x;
    int f = gid >> 12;
    int e = gid & 4095;
    int n = e >> 6, m = e & 63;
    double sum = 0.0;
    if (n != m) {
        int b0, nb;
        if (f < FA) { b0 = f * BLKS_PER_A; nb = BLKS_PER_A; }
        else        { b0 = FA * BLKS_PER_A + (f - FA) * BLKS_PER_B; nb = BLKS_PER_B; }
        for (int bb = 0; bb < nb; bb++) sum += (double)g_part[b0 + bb][e];
    }
    g_Kd[f][e] = sum;
}

// ---------------------------------------------------------------------------
// Phase 3: parallel reduction tail.
// blocks 0..24  : tr(Ki Kj) for each in-group pair (dot over 4096 doubles)
// blocks 25..31 : row sums of K_f (64 threads, one row each)
// ---------------------------------------------------------------------------
__global__ void pair_dots() {
    int b = blockIdx.x;
    int tid = threadIdx.x;
    if (b < 25) {
        int fi, fj;
        if (b < 9) { fi = b / 3; fj = b % 3; }
        else       { int q = b - 9; fi = 3 + q / 4; fj = 3 + q % 4; }
        const double* Ki = g_Kd[fi];
        const double* Kj = g_Kd[fj];
        double part = 0.0;
#pragma unroll 4
        for (int e = tid; e < 4096; e += 256) part += Ki[e] * Kj[e];
        __shared__ double red[256];
        red[tid] = part;
        __syncthreads();
        for (int s = 128; s > 0; s >>= 1) {
            if (tid < s) red[tid] += red[tid + s];
            __syncthreads();
        }
        if (tid == 0) g_trkl[b] = red[0];
    } else {
        int f = b - 25;
        if (tid < 64) {
            const double* K = g_Kd[f] + tid * 64;
            double rs = 0.0;
#pragma unroll 8
            for (int m = 0; m < 64; m++) rs += K[m];
            g_rsum[f][tid] = rs;
        }
    }
}

// ---------------------------------------------------------------------------
// CE: one block per row. Target dtype detected on-device (int32 vs int64)
// without reading past the minimal int32 footprint.
// ---------------------------------------------------------------------------
__global__ void ce_kernel(const float* __restrict__ logits,
                          const void* __restrict__ tgt_raw) {
    int row = blockIdx.x;
    const float* x = logits + row * NCLS;
    __shared__ float  redf[256];
    __shared__ double redd[256];
    int tid = threadIdx.x;

    float m = -1e30f;
    for (int c = tid; c < NCLS; c += 256) m = fmaxf(m, x[c]);
    redf[tid] = m;
    __syncthreads();
    for (int s = 128; s > 0; s >>= 1) {
        if (tid < s) redf[tid] = fmaxf(redf[tid], redf[tid + s]);
        __syncthreads();
    }
    float M = redf[0];
    __syncthreads();

    double se = 0.0;
    for (int c = tid; c < NCLS; c += 256) se += exp((double)(x[c] - M));
    redd[tid] = se;
    __syncthreads();
    for (int s = 128; s > 0; s >>= 1) {
        if (tid < s) redd[tid] += redd[tid + s];
        __syncthreads();
    }
    if (tid == 0) {
        const int* ti = (const int*)tgt_raw;
        bool odd_zero = true;
        for (int k = 1; k < 64; k += 2) odd_zero &= (ti[k] == 0);
        long long t;
        if (odd_zero) t = ((const long long*)tgt_raw)[row];  // int64 layout
        else          t = (long long)ti[row];                // int32 layout
        if (t < 0 || t >= NCLS) t = 0;
        g_ce_row[row] = -((double)x[t] - (double)M - log(redd[0]));
    }
}

// ---------------------------------------------------------------------------
// Finalize: tiny scalar combine. All big reductions already done.
// ---------------------------------------------------------------------------
__global__ void finalize(float* __restrict__ out) {
    if (threadIdx.x != 0) return;
    const double c1 = 63.0 * 62.0;   // (N-1)(N-2)
    const double c2 = 62.0;          // (N-2)
    const double c3 = 64.0 * 61.0;   // N(N-3)
    double s_[7];
    for (int f = 0; f < 7; f++) {
        double a = 0.0;
        for (int n = 0; n < 64; n++) a += g_rsum[f][n];
        s_[f] = a;
    }
    double cka = 0.0;
    for (int g = 0; g < 2; g++) {
        int F = g ? 4 : 3;
        int base = g ? 3 : 0;
        int pbase = g ? 9 : 0;
        double hs[4][4], dd[4];
        for (int i = 0; i < F; i++)
            for (int j = 0; j < F; j++) {
                double trkl = g_trkl[pbase + i * F + j];
                double rr = 0.0;
                for (int n = 0; n < 64; n++)
                    rr += g_rsum[base + i][n] * g_rsum[base + j][n];
                hs[i][j] = (trkl + s_[base + i] * s_[base + j] / c1 -
                            2.0 * rr / c2) / c3;
            }
        for (int i = 0; i < F; i++) dd[i] = sqrt(hs[i][i]);
        for (int i = 0; i < F; i++)
            for (int j = 0; j < F; j++)
                cka += hs[i][j] / (dd[i] * dd[j]);
    }
    double ce = 0.0;
    for (int n = 0; n < NROW; n++) ce += g_ce_row[n];
    ce /= (double)NROW;
    out[0] = (float)(ce + 0.1 * cka);
}

// ---------------------------------------------------------------------------
extern "C" void kernel_launch(void* const* d_in, const int* in_sizes, int n_in,
                              void* d_out, int out_size) {
    // Identify inputs by element count -- robust to metadata ordering.
    const float* logits = nullptr;
    const void*  tgt    = nullptr;
    const float* fa     = nullptr;
    const float* fb     = nullptr;
    for (int i = 0; i < n_in; i++) {
        int s = in_sizes[i];
        if (s == NROW * NCLS)           logits = (const float*)d_in[i];
        else if (s == NROW)             tgt    = d_in[i];
        else if (s == FA * NROW * DA)   fa     = (const float*)d_in[i];
        else if (s == FB * NROW * DB)   fb     = (const float*)d_in[i];
    }
    float* out = (float*)d_out;

    ce_kernel<<<NROW, 256>>>(logits, tgt);
    gram_partial<<<GRID1, 256>>>(fa, fb);
    gram_reduce<<<112, 256>>>();
    pair_dots<<<32, 256>>>();
    finalize<<<1, 32>>>(out);
    // passthrough of `output` (second tuple element)
    cudaMemcpyAsync(out + 1, logits, NROW * NCLS * sizeof(float),
                    cudaMemcpyDeviceToDevice, 0);
}

// round 7
// speedup vs baseline: 1.9788x; 1.4479x over previous
#include <cuda_runtime.h>
#include <cstdint>
#include <math.h>

// ---------------------------------------------------------------------------
// Problem constants
//   output  [64,1000] f32, target [64] int, feats_a [3,64,65536] f32,
//   feats_b [4,64,32768] f32;   out = [loss(1), output(64000)] f32
// ---------------------------------------------------------------------------
#define NROW 64
#define NCLS 1000
#define FA 3
#define DA 65536
#define FB 4
#define DB 32768
#define BLKS_PER_A 29          // 3*29 = 87 blocks for group a
#define BLKS_PER_B 15          // 4*15 = 60 blocks for group b
#define GRID1 (FA * BLKS_PER_A + FB * BLKS_PER_B)   // 147 (one wave on 148 SMs)
#define TILES_A (DA / 64)      // 1024
#define TILES_B (DB / 64)      // 512

// Scratch (no allocations allowed -> __device__ globals)
__device__ float  g_part[GRID1][4096];   // per-block partial Gram matrices
__device__ double g_Kd[7][4096];         // final Gram matrices (diag zeroed), f64
__device__ double g_ce_row[NROW];        // per-row CE contributions
__device__ double g_trkl[25];            // tr(Ki Kj) per in-group pair
__device__ double g_rsum[7][64];         // row sums of each K

// ---------------------------------------------------------------------------
// Phase 1: partial Gram K = X X^T over a D-range, fp32 register tiles.
// 256 threads = 16x16 grid, each thread owns a 4x4 tile of the 64x64 output.
// ---------------------------------------------------------------------------
__global__ __launch_bounds__(256, 1) void gram_partial(
    const float* __restrict__ A, const float* __restrict__ B) {
    int b = blockIdx.x;
    const float* X;
    long long D;
    int t0, t1;
    if (b < FA * BLKS_PER_A) {
        int f = b / BLKS_PER_A, lb = b % BLKS_PER_A;
        X = A + (long long)f * NROW * DA;
        D = DA;
        t0 = lb * TILES_A / BLKS_PER_A;
        t1 = (lb + 1) * TILES_A / BLKS_PER_A;
    } else {
        int bb = b - FA * BLKS_PER_A;
        int f = bb / BLKS_PER_B, lb = bb % BLKS_PER_B;
        X = B + (long long)f * NROW * DB;
        D = DB;
        t0 = lb * TILES_B / BLKS_PER_B;
        t1 = (lb + 1) * TILES_B / BLKS_PER_B;
    }

    __shared__ float4 Xs[64][16];   // 16 KB

    int tid = threadIdx.x;
    int tx = tid & 15, ty = tid >> 4;

    float acc[4][4];
#pragma unroll
    for (int i = 0; i < 4; i++)
#pragma unroll
        for (int j = 0; j < 4; j++) acc[i][j] = 0.f;

    // prefetch first tile into registers
    float4 pf[4];
#pragma unroll
    for (int i = 0; i < 4; i++) {
        int idx = tid + i * 256;
        int row = idx >> 4, c4 = idx & 15;
        pf[i] = *(const float4*)(X + (long long)row * D + (long long)t0 * 64 + 4 * c4);
    }

    for (int tt = t0; tt < t1; tt++) {
        __syncthreads();
#pragma unroll
        for (int i = 0; i < 4; i++) {
            int idx = tid + i * 256;
            int row = idx >> 4, c4 = idx & 15;
            Xs[row][c4 ^ ((row >> 2) & 7)] = pf[i];
        }
        __syncthreads();
        if (tt + 1 < t1) {
#pragma unroll
            for (int i = 0; i < 4; i++) {
                int idx = tid + i * 256;
                int row = idx >> 4, c4 = idx & 15;
                pf[i] = *(const float4*)(X + (long long)row * D +
                                         (long long)(tt + 1) * 64 + 4 * c4);
            }
        }
#pragma unroll 4
        for (int k4 = 0; k4 < 16; k4++) {
            float4 af[4], bf[4];
#pragma unroll
            for (int i = 0; i < 4; i++) af[i] = Xs[4 * ty + i][k4 ^ (ty & 7)];
#pragma unroll
            for (int i = 0; i < 4; i++) bf[i] = Xs[4 * tx + i][k4 ^ (tx & 7)];
#pragma unroll
            for (int i = 0; i < 4; i++)
#pragma unroll
                for (int j = 0; j < 4; j++) {
                    acc[i][j] += af[i].x * bf[j].x;
                    acc[i][j] += af[i].y * bf[j].y;
                    acc[i][j] += af[i].z * bf[j].z;
                    acc[i][j] += af[i].w * bf[j].w;
                }
        }
    }

    float* P = g_part[b];
#pragma unroll
    for (int i = 0; i < 4; i++)
#pragma unroll
        for (int j = 0; j < 4; j++)
            P[(4 * ty + i) * 64 + 4 * tx + j] = acc[i][j];
}

// ---------------------------------------------------------------------------
// Phase 2: reduce partials -> K (double), zero the diagonal.
// ---------------------------------------------------------------------------
__global__ void gram_reduce() {
    int gid = blockIdx.x * 256 + threadIdx.x;
    int f = gid >> 12;
    int e = gid & 4095;
    int n = e >> 6, m = e & 63;
    double sum = 0.0;
    if (n != m) {
        int b0, nb;
        if (f < FA) { b0 = f * BLKS_PER_A; nb = BLKS_PER_A; }
        else        { b0 = FA * BLKS_PER_A + (f - FA) * BLKS_PER_B; nb = BLKS_PER_B; }
        for (int bb = 0; bb < nb; bb++) sum += (double)g_part[b0 + bb][e];
    }
    g_Kd[f][e] = sum;
}

// ---------------------------------------------------------------------------
// Phase 3: parallel reduction tail.
// blocks 0..24  : tr(Ki Kj) for each in-group pair (dot over 4096 doubles)
// blocks 25..31 : row sums of K_f (64 threads, one row each)
// ---------------------------------------------------------------------------
__global__ void pair_dots() {
    int b = blockIdx.x;
    int tid = threadIdx.x;
    if (b < 25) {
        int fi, fj;
        if (b < 9) { fi = b / 3; fj = b % 3; }
        else       { int q = b - 9; fi = 3 + q / 4; fj = 3 + q % 4; }
        const double* Ki = g_Kd[fi];
        const double* Kj = g_Kd[fj];
        double part = 0.0;
#pragma unroll 4
        for (int e = tid; e < 4096; e += 256) part += Ki[e] * Kj[e];
        __shared__ double red[256];
        red[tid] = part;
        __syncthreads();
        for (int s = 128; s > 0; s >>= 1) {
            if (tid < s) red[tid] += red[tid + s];
            __syncthreads();
        }
        if (tid == 0) g_trkl[b] = red[0];
    } else {
        int f = b - 25;
        if (tid < 64) {
            const double* K = g_Kd[f] + tid * 64;
            double rs = 0.0;
#pragma unroll 8
            for (int m = 0; m < 64; m++) rs += K[m];
            g_rsum[f][tid] = rs;
        }
    }
}

// ---------------------------------------------------------------------------
// CE: one block per row. Target dtype detected on-device (int32 vs int64)
// without reading past the minimal int32 footprint.
// ---------------------------------------------------------------------------
__global__ void ce_kernel(const float* __restrict__ logits,
                          const void* __restrict__ tgt_raw) {
    int row = blockIdx.x;
    const float* x = logits + row * NCLS;
    __shared__ float  redf[256];
    __shared__ double redd[256];
    int tid = threadIdx.x;

    float m = -1e30f;
    for (int c = tid; c < NCLS; c += 256) m = fmaxf(m, x[c]);
    redf[tid] = m;
    __syncthreads();
    for (int s = 128; s > 0; s >>= 1) {
        if (tid < s) redf[tid] = fmaxf(redf[tid], redf[tid + s]);
        __syncthreads();
    }
    float M = redf[0];
    __syncthreads();

    double se = 0.0;
    for (int c = tid; c < NCLS; c += 256) se += exp((double)(x[c] - M));
    redd[tid] = se;
    __syncthreads();
    for (int s = 128; s > 0; s >>= 1) {
        if (tid < s) redd[tid] += redd[tid + s];
        __syncthreads();
    }
    if (tid == 0) {
        const int* ti = (const int*)tgt_raw;
        bool odd_zero = true;
        for (int k = 1; k < 64; k += 2) odd_zero &= (ti[k] == 0);
        long long t;
        if (odd_zero) t = ((const long long*)tgt_raw)[row];  // int64 layout
        else          t = (long long)ti[row];                // int32 layout
        if (t < 0 || t >= NCLS) t = 0;
        g_ce_row[row] = -((double)x[t] - (double)M - log(redd[0]));
    }
}

// ---------------------------------------------------------------------------
// Finalize: stage everything into shared cooperatively, reduce in parallel,
// leave only ~300 shared-resident flops on thread 0. No serial global loads.
// ---------------------------------------------------------------------------
__global__ __launch_bounds__(256, 1) void finalize(float* __restrict__ out) {
    __shared__ double r_sh[7 * 64];     // row sums
    __shared__ double trkl_sh[25];
    __shared__ double s_sh[7];          // total sums
    __shared__ double rr_sh[25];        // <r_i, r_j> per pair
    __shared__ double ce_red[64];
    int tid = threadIdx.x;

    // cooperative staging: 448 + 25 + 64 loads, fully parallel
    for (int idx = tid; idx < 7 * 64; idx += 256)
        r_sh[idx] = ((const double*)g_rsum)[idx];
    if (tid < 25) trkl_sh[tid] = g_trkl[tid];
    if (tid < 64) ce_red[tid] = g_ce_row[tid];
    __syncthreads();

    // total sums (7 threads x 64 LDS each)
    if (tid < 7) {
        double a = 0.0;
#pragma unroll 8
        for (int n = 0; n < 64; n++) a += r_sh[tid * 64 + n];
        s_sh[tid] = a;
    }
    // rr dot products (25 threads x 64 LDS pairs each)
    if (tid >= 32 && tid < 57) {
        int p = tid - 32;
        int fi, fj;
        if (p < 9) { fi = p / 3; fj = p % 3; }
        else       { int q = p - 9; fi = 3 + q / 4; fj = 3 + q % 4; }
        double rr = 0.0;
#pragma unroll 8
        for (int n = 0; n < 64; n++)
            rr += r_sh[fi * 64 + n] * r_sh[fj * 64 + n];
        rr_sh[p] = rr;
    }
    // CE tree reduction in the 64..127 thread range's shared slot
    __syncthreads();
    for (int s = 32; s > 0; s >>= 1) {
        if (tid < s) ce_red[tid] += ce_red[tid + s];
        __syncthreads();
    }

    if (tid == 0) {
        const double c1 = 63.0 * 62.0;   // (N-1)(N-2)
        const double c2 = 62.0;          // (N-2)
        const double c3 = 64.0 * 61.0;   // N(N-3)
        double cka = 0.0;
        for (int g = 0; g < 2; g++) {
            int F = g ? 4 : 3;
            int base = g ? 3 : 0;
            int pbase = g ? 9 : 0;
            double hs[4][4], dd[4];
            for (int i = 0; i < F; i++)
                for (int j = 0; j < F; j++) {
                    int p = pbase + i * F + j;
                    hs[i][j] = (trkl_sh[p] +
                                s_sh[base + i] * s_sh[base + j] / c1 -
                                2.0 * rr_sh[p] / c2) / c3;
                }
            for (int i = 0; i < F; i++) dd[i] = sqrt(hs[i][i]);
            for (int i = 0; i < F; i++)
                for (int j = 0; j < F; j++)
                    cka += hs[i][j] / (dd[i] * dd[j]);
        }
        double ce = ce_red[0] / (double)NROW;
        out[0] = (float)(ce + 0.1 * cka);
    }
}

// ---------------------------------------------------------------------------
extern "C" void kernel_launch(void* const* d_in, const int* in_sizes, int n_in,
                              void* d_out, int out_size) {
    // Identify inputs by element count -- robust to metadata ordering.
    const float* logits = nullptr;
    const void*  tgt    = nullptr;
    const float* fa     = nullptr;
    const float* fb     = nullptr;
    for (int i = 0; i < n_in; i++) {
        int s = in_sizes[i];
        if (s == NROW * NCLS)           logits = (const float*)d_in[i];
        else if (s == NROW)             tgt    = d_in[i];
        else if (s == FA * NROW * DA)   fa     = (const float*)d_in[i];
        else if (s == FB * NROW * DB)   fb     = (const float*)d_in[i];
    }
    float* out = (float*)d_out;

    ce_kernel<<<NROW, 256>>>(logits, tgt);
    gram_partial<<<GRID1, 256>>>(fa, fb);
    gram_reduce<<<112, 256>>>();
    pair_dots<<<32, 256>>>();
    finalize<<<1, 256>>>(out);
    // passthrough of `output` (second tuple element)
    cudaMemcpyAsync(out + 1, logits, NROW * NCLS * sizeof(float),
                    cudaMemcpyDeviceToDevice, 0);
}